// round 15
// baseline (speedup 1.0000x reference)
#include <cuda_runtime.h>

// FlowNetC correlation on GB300 — round 15: A via fragment-ordered gmem scratch
// + direct LDG.128 to registers (no smem round-trip for A). B unchanged from
// R14: warp-autonomous cp.async 3-stage ring + ldmatrix.x4. Banded m16n8k8
// tf32 MMA; prepass bakes rna-tf32 conversion, parity de-interleave, 1/256.
//
// out[b, dy*21+dx, y, x] = (1/256) * sum_c in1[b,c,y,x] * in2[b,c, y+2dy-20, x+2dx-20]

#define DD      21
#define HH      96
#define WW      128
#define NCH     32
#define NDY     3
#define NTH     192

// per-warp B region (words): [kh2][u96][4] = 768 per stage, 3 stages
#define WSTG    768
#define WSTG_B  (WSTG * 4)           // 3072 bytes
#define NSTG    3
#define WREG    (NSTG * WSTG)        // 2304 words per warp
#define SMEM_WORDS (6 * WREG)        // 13824 words = 55296 B per block

#define ELEMS   (8 * 256 * 96 * 128)
#define CSTEP   (2 * 96 * 2 * 64 * 4)   // B scratch: +2 c4 per chunk
#define KHSTEP  (96 * 2 * 64 * 4)
#define A4STEP  (96 * 256)              // A2 scratch float4 stride per k8

__device__ float g2t[ELEMS];    // B scratch (in2, tf32 bits, deinterleaved)
__device__ float g1f[ELEMS];    // A2 scratch (in1*1/256, fragment-ordered)

__device__ __forceinline__ unsigned cvt_tf32(float v) {
    unsigned r;
    asm("cvt.rna.tf32.f32 %0, %1;" : "=r"(r) : "f"(v));
    return r;
}
__device__ __forceinline__ void cp16(unsigned dst, const float* src) {
    asm volatile("cp.async.cg.shared.global [%0], [%1], 16;"
                 :: "r"(dst), "l"(src));
}
__device__ __forceinline__ void ldsm4(unsigned addr, unsigned& r0, unsigned& r1,
                                      unsigned& r2, unsigned& r3) {
    asm volatile("ldmatrix.sync.aligned.m8n8.x4.shared.b16 {%0,%1,%2,%3}, [%4];"
                 : "=r"(r0), "=r"(r1), "=r"(r2), "=r"(r3) : "r"(addr));
}
__device__ __forceinline__ void mma_tf32(float (&d)[4],
                                         unsigned a0, unsigned a1,
                                         unsigned a2, unsigned a3,
                                         unsigned b0, unsigned b1) {
    asm volatile(
        "mma.sync.aligned.m16n8k8.row.col.f32.tf32.tf32.f32 "
        "{%0,%1,%2,%3}, {%4,%5,%6,%7}, {%8,%9}, {%0,%1,%2,%3};"
        : "+f"(d[0]), "+f"(d[1]), "+f"(d[2]), "+f"(d[3])
        : "r"(a0), "r"(a1), "r"(a2), "r"(a3), "r"(b0), "r"(b1));
}

// ---- prepass B: cvt + transpose in2 -> [b][c4][y][par][xh][cc4] ----
__global__ void __launch_bounds__(128) prepassB(const float* __restrict__ s2)
{
    const int x   = threadIdx.x;
    const int y   = blockIdx.x;
    const int c4  = blockIdx.y;
    const int b   = blockIdx.z;
    const size_t plane = (size_t)HH * WW;
    const float* src = s2 + ((size_t)(b * 256 + c4 * 4) * HH + y) * WW + x;
    unsigned v0 = cvt_tf32(src[0]);
    unsigned v1 = cvt_tf32(src[plane]);
    unsigned v2 = cvt_tf32(src[2 * plane]);
    unsigned v3 = cvt_tf32(src[3 * plane]);
    size_t o = ((((size_t)b * 64 + c4) * HH + y) * 2 + (x & 1)) * 64 + (x >> 1);
    ((uint4*)g2t)[o] = make_uint4(v0, v1, v2, v3);
}

// ---- prepass A: fragment-ordered A2 so each lane LDG.128s its mma fragment.
// A2[(b*32+k8)*96+y][o], o = par*512 + mt*128 + lane*4 + e  (floats)
// value = in1[b][k8*8 + t + 4*(e>>1)][y][2*(16mt + g + 8*(e&1)) + par] / 256
__global__ void __launch_bounds__(128) prepassA(const float* __restrict__ s1)
{
    __shared__ float s[8][128];
    const int tid = threadIdx.x;
    const int y   = blockIdx.x;     // 96
    const int k8  = blockIdx.y;     // 32
    const int b   = blockIdx.z;     // 8
    const size_t plane = (size_t)HH * WW;
    const float* src = s1 + ((size_t)(b * 256 + k8 * 8) * HH + y) * WW + tid;
    #pragma unroll
    for (int cc = 0; cc < 8; ++cc)
        s[cc][tid] = src[cc * plane] * (1.0f / 256.0f);
    __syncthreads();
    float* outp = g1f + (((size_t)b * 32 + k8) * HH + y) * 1024;
    #pragma unroll
    for (int i = 0; i < 8; ++i) {
        int o   = tid + 128 * i;
        int par = o >> 9;
        int r   = o & 511;
        int mt  = r >> 7;
        int s2i = r & 127;
        int l   = s2i >> 2;
        int e   = s2i & 3;
        int g   = l >> 2, t = l & 3;
        int cc  = t + 4 * (e >> 1);
        int x   = 2 * (16 * mt + g + 8 * (e & 1)) + par;
        unsigned bits = cvt_tf32(s[cc][x]);
        outp[o] = __uint_as_float(bits);
    }
}

extern __shared__ unsigned smw[];

__global__ void __launch_bounds__(NTH, 2) corr_mma(float* __restrict__ g_out)
{
    const int b    = blockIdx.z;
    const int y    = blockIdx.y;
    const int dyg  = blockIdx.x;      // 0..6
    const int tid  = threadIdx.x;
    const int lane = tid & 31;
    const int w    = tid >> 5;        // 0..5
    const int par  = w & 1;
    const int dyl  = w >> 1;          // 0..2
    const int dy   = dyg * NDY + dyl;
    const int g    = lane >> 2;
    const int t    = lane & 3;

    const size_t plane = (size_t)HH * WW;
    const int wb = w * WREG;

    // Each warp zeros ONLY its own B region (pads + OOB rows stay zero).
    for (int i = lane; i < WREG; i += 32) smw[wb + i] = 0u;
    __syncwarp();

    const unsigned sm0 = (unsigned)__cvta_generic_to_shared(smw);
    const unsigned wbB = sm0 + (unsigned)wb * 4u;

    const int  row2 = y + 2 * dy - 20;
    const bool rok  = (row2 >= 0) && (row2 < HH);

    // ---- B cp.async bases (4 copies per lane per chunk) ----
    const float* bp = g2t + ((size_t)(((b * 64) * HH + (rok ? row2 : 0)) * 2
                                      + par) * 64 + lane) * 4;
    const unsigned bdst = wbB + (unsigned)((10 + lane) * 4) * 4u;

    // ---- A fragment LDG base (float4 units) ----
    const uint4* ag = (const uint4*)g1f
        + (((size_t)b * 32) * HH + y) * 256 + par * 128 + lane;

    // ---- B ldmatrix lane bases ----
    const unsigned bl_kh = (lane >> 3) & 1;
    const unsigned bl_u  = ((lane >> 4) << 3) + (lane & 7);
    const unsigned bLds  = wbB + (bl_kh * 384 + bl_u * 4) * 4u;

    float acc[20][4];
    #pragma unroll
    for (int f = 0; f < 20; ++f)
        #pragma unroll
        for (int e = 0; e < 4; ++e) acc[f][e] = 0.0f;

    auto issue_chunk = [&](int stg) {
        const unsigned sb = (unsigned)stg * WSTG_B;
        if (rok) {
            cp16(bdst + sb,              bp);               // kh0, u=lane
            cp16(bdst + sb + 512,        bp + 128);         // kh0, u=lane+32
            cp16(bdst + sb + 1536,       bp + KHSTEP);      // kh1, u=lane
            cp16(bdst + sb + 1536 + 512, bp + KHSTEP + 128);
        }
        bp += CSTEP;
    };

    issue_chunk(0); asm volatile("cp.async.commit_group;");
    issue_chunk(1); asm volatile("cp.async.commit_group;");
    issue_chunk(2); asm volatile("cp.async.commit_group;");

    // A double-buffer in registers; prologue loads chunk 0
    uint4 af[2][4];
    #pragma unroll
    for (int mt = 0; mt < 4; ++mt)
        af[0][mt] = __ldg(ag + mt * 32);

    int stg = 0;
    #pragma unroll 2
    for (int k = 0; k < NCH; ++k) {
        asm volatile("cp.async.wait_group 2;");   // own B chunk-k copies done
        __syncwarp();

        // prefetch A for chunk k+1 (independent of smem ring)
        if (k + 1 < NCH) {
            const uint4* agn = ag + (size_t)(k + 1) * A4STEP;
            #pragma unroll
            for (int mt = 0; mt < 4; ++mt)
                af[(k + 1) & 1][mt] = __ldg(agn + mt * 32);
        }

        const unsigned sb = (unsigned)stg * WSTG_B;
        const uint4 (&a)[4] = af[k & 1];

        // B fragments + MMAs (j-outer, tile pair per ldsm.x4)
        #pragma unroll
        for (int jp = 0; jp < 6; ++jp) {
            unsigned b0, b1, b2, b3;
            ldsm4(bLds + sb + jp * 256, b0, b1, b2, b3);
            const int j0 = 2 * jp;
            #pragma unroll
            for (int mt = 0; mt < 4; ++mt)
                if (2 * mt <= j0 && j0 <= 2 * mt + 4)
                    mma_tf32(acc[mt * 5 + (j0 - 2 * mt)],
                             a[mt].x, a[mt].y, a[mt].z, a[mt].w, b0, b1);
            const int j1 = j0 + 1;
            if (j1 < 11) {
                #pragma unroll
                for (int mt = 0; mt < 4; ++mt)
                    if (2 * mt <= j1 && j1 <= 2 * mt + 4)
                        mma_tf32(acc[mt * 5 + (j1 - 2 * mt)],
                                 a[mt].x, a[mt].y, a[mt].z, a[mt].w, b2, b3);
            }
        }

        // refill freed B stage AFTER this chunk's MMAs (WAR-safe in-warp)
        if (k + 3 < NCH) issue_chunk(stg);
        asm volatile("cp.async.commit_group;");   // uniform group counting

        stg = (stg == 2) ? 0 : stg + 1;
    }

    // ---- epilogue: band-extract + scatter stores (1/256 pre-baked in A) ----
    float* ob = g_out + ((size_t)(b * (DD * DD) + dy * DD)) * plane
                      + (size_t)y * WW + par;
    #pragma unroll
    for (int mt = 0; mt < 4; ++mt) {
        #pragma unroll
        for (int i = 0; i < 5; ++i) {
            const int u0 = 8 * (2 * mt + i);
            const float* f = acc[mt * 5 + i];
            #pragma unroll
            for (int e = 0; e < 4; ++e) {
                int r   = (e >= 2) ? (g + 8) : g;
                int col = 2 * t + (e & 1);
                int xh  = 16 * mt + r;
                int dx  = u0 + col - xh;
                if (dx >= 0 && dx < DD)
                    ob[(size_t)dx * plane + 2 * xh] = f[e];
            }
        }
    }
}

extern "C" void kernel_launch(void* const* d_in, const int* in_sizes, int n_in,
                              void* d_out, int out_size)
{
    (void)in_sizes; (void)n_in; (void)out_size;
    const float* in1 = (const float*)d_in[0];
    const float* in2 = (const float*)d_in[1];
    float*       out = (float*)d_out;

    // prepasses: B (deinterleaved k-contig) and A (fragment-ordered)
    prepassB<<<dim3(HH, 64, 8), 128>>>(in2);
    prepassA<<<dim3(HH, 32, 8), 128>>>(in1);

    // main banded MMA, warp-autonomous
    cudaFuncSetAttribute(corr_mma, cudaFuncAttributeMaxDynamicSharedMemorySize,
                         SMEM_WORDS * 4);
    dim3 grid(7, HH, 8);     // (dy-group of 3, y, b) -> 5376 blocks
    corr_mma<<<grid, NTH, SMEM_WORDS * 4>>>(out);
}